// round 1
// baseline (speedup 1.0000x reference)
#include <cuda_runtime.h>
#include <math.h>

#define BB 128
#define DD 512
#define TT 1024
#define GG 256
#define KK 32
#define HH 64
#define CC 4

// Scratch (allocation-free rule: __device__ globals)
__device__ float g_KV[BB*KK];
__device__ float g_u[BB*DD];
__device__ float g_c[BB*DD];
__device__ float g_Sc[BB];
__device__ float g_Scc[BB];
__device__ float g_scores[BB*TT];
__device__ float g_S1[BB*TT];
__device__ float g_S2[BB*TT];
__device__ float g_Sxc[BB*TT];
__device__ float g_rstd[BB*TT];
__device__ float g_R1[BB];
__device__ float g_R2[BB];
__device__ float g_A[BB*DD];

__device__ __forceinline__ float warpSum(float v) {
    #pragma unroll
    for (int o = 16; o > 0; o >>= 1) v += __shfl_xor_sync(0xffffffffu, v, o);
    return v;
}
__device__ __forceinline__ float warpMax(float v) {
    #pragma unroll
    for (int o = 16; o > 0; o >>= 1) v = fmaxf(v, __shfl_xor_sync(0xffffffffu, v, o));
    return v;
}

// Kernel 1: per-batch tiny precompute.
// KV[b,k] = sum_g gaf[b,g]*Wkv[k,g]
// u[b,d]  = sum_k Wq[k,d]*KV[b,k]
// c[b,d]  = sum_k KV[b,k]*Wout[d,k]
// Sc[b] = sum_d c ; Scc[b] = sum_d c^2
__global__ void k1_prep(const float* __restrict__ gaf, const float* __restrict__ Wq,
                        const float* __restrict__ Wkv, const float* __restrict__ Wout) {
    int b = blockIdx.x, tid = threadIdx.x;
    __shared__ float s_gaf[GG];
    __shared__ float s_kv[KK];
    __shared__ float red1[8], red2[8];

    s_gaf[tid] = gaf[b * GG + tid];
    __syncthreads();

    if (tid < KK) {
        float acc = 0.f;
        #pragma unroll 8
        for (int g = 0; g < GG; g++) acc += s_gaf[g] * Wkv[tid * GG + g];
        s_kv[tid] = acc;
        g_KV[b * KK + tid] = acc;
    }
    __syncthreads();

    float lsc = 0.f, lscc = 0.f;
    for (int d = tid; d < DD; d += 256) {
        float uu = 0.f, cc = 0.f;
        #pragma unroll
        for (int k = 0; k < KK; k++) {
            uu += Wq[k * DD + d] * s_kv[k];
            cc += s_kv[k] * Wout[d * KK + k];
        }
        g_u[b * DD + d] = uu;
        g_c[b * DD + d] = cc;
        lsc += cc; lscc += cc * cc;
    }
    lsc = warpSum(lsc); lscc = warpSum(lscc);
    int wid = tid >> 5, lane = tid & 31;
    if (lane == 0) { red1[wid] = lsc; red2[wid] = lscc; }
    __syncthreads();
    if (tid == 0) {
        float a = 0.f, bb = 0.f;
        for (int i = 0; i < 8; i++) { a += red1[i]; bb += red2[i]; }
        g_Sc[b] = a; g_Scc[b] = bb;
    }
}

// Kernel 2: pass 1 over tcf [B,D,T]. Thread t (coalesced along T) loops d.
// Produces scores, S1, S2, Sxc per (b,t).
__global__ void k2_pass1(const float* __restrict__ tcf) {
    int b = blockIdx.y;
    int t = blockIdx.x * 256 + threadIdx.x;
    __shared__ float su[DD], scs[DD];
    for (int i = threadIdx.x; i < DD; i += 256) {
        su[i]  = g_u[b * DD + i];
        scs[i] = g_c[b * DD + i];
    }
    __syncthreads();

    const float* xp = tcf + (size_t)b * DD * TT + t;
    float dot = 0.f, s1 = 0.f, s2 = 0.f, sxc = 0.f;
    #pragma unroll 8
    for (int d = 0; d < DD; d++) {
        float xv = xp[(size_t)d * TT];
        dot += xv * su[d];
        s1  += xv;
        s2  += xv * xv;
        sxc += xv * scs[d];
    }
    int idx = b * TT + t;
    g_scores[idx] = dot * 0.17677669529663687f;  // DK^-0.5 = 1/sqrt(32)
    g_S1[idx] = s1;
    g_S2[idx] = s2;
    g_Sxc[idx] = sxc;
}

// Kernel 3: softmax over T per b, rstd per (b,t), and R1 = sum rstd*w, R2 = sum rstd*mu.
__global__ void k3_softmax() {
    int b = blockIdx.x, tid = threadIdx.x;
    int wid = tid >> 5, lane = tid & 31;
    __shared__ float red[8], redb[8];
    __shared__ float bval;

    float sc[4];
    float m = -1e30f;
    #pragma unroll
    for (int i = 0; i < 4; i++) {
        sc[i] = g_scores[b * TT + tid + i * 256];
        m = fmaxf(m, sc[i]);
    }
    m = warpMax(m);
    if (lane == 0) red[wid] = m;
    __syncthreads();
    if (tid == 0) {
        float mm = red[0];
        for (int i = 1; i < 8; i++) mm = fmaxf(mm, red[i]);
        bval = mm;
    }
    __syncthreads();
    m = bval;

    float e[4], se = 0.f;
    #pragma unroll
    for (int i = 0; i < 4; i++) { e[i] = expf(sc[i] - m); se += e[i]; }
    se = warpSum(se);
    __syncthreads();
    if (lane == 0) red[wid] = se;
    __syncthreads();
    if (tid == 0) {
        float s = 0.f;
        for (int i = 0; i < 8; i++) s += red[i];
        bval = s;
    }
    __syncthreads();
    float inv = 1.f / bval;

    float Scb = g_Sc[b], Sccb = g_Scc[b];
    float r1 = 0.f, r2 = 0.f;
    #pragma unroll
    for (int i = 0; i < 4; i++) {
        int idx = b * TT + tid + i * 256;
        float w = e[i] * inv;
        float mu = (g_S1[idx] + w * Scb) * (1.f / DD);
        float ms = (g_S2[idx] + 2.f * w * g_Sxc[idx] + w * w * Sccb) * (1.f / DD);
        float var = ms - mu * mu;
        float rstd = rsqrtf(var + 1e-5f);
        g_rstd[idx] = rstd;
        r1 += rstd * w;
        r2 += rstd * mu;
    }
    r1 = warpSum(r1); r2 = warpSum(r2);
    __syncthreads();
    if (lane == 0) { red[wid] = r1; redb[wid] = r2; }
    __syncthreads();
    if (tid == 0) {
        float a = 0.f, c = 0.f;
        for (int i = 0; i < 8; i++) { a += red[i]; c += redb[i]; }
        g_R1[b] = a; g_R2[b] = c;
    }
}

// Kernel 4: pass 2 over tcf. A[b,d] = sum_t rstd[b,t]*x[b,d,t]. One block per (d,b).
__global__ void k4_A(const float* __restrict__ tcf) {
    int d = blockIdx.x, b = blockIdx.y, tid = threadIdx.x;
    const float* xp = tcf + ((size_t)b * DD + d) * TT;
    const float* rp = g_rstd + b * TT;
    float acc = 0.f;
    #pragma unroll
    for (int i = 0; i < 4; i++) {
        int t = tid + i * 256;
        acc += xp[t] * rp[t];
    }
    acc = warpSum(acc);
    __shared__ float red[8];
    int wid = tid >> 5, lane = tid & 31;
    if (lane == 0) red[wid] = acc;
    __syncthreads();
    if (tid == 0) {
        float s = 0.f;
        for (int i = 0; i < 8; i++) s += red[i];
        g_A[b * DD + d] = s;
    }
}

// Kernel 5: pooled + MLP head + output.
__global__ void k5_head(const float* __restrict__ ln1g, const float* __restrict__ ln1b,
                        const float* __restrict__ W1, const float* __restrict__ b1,
                        const float* __restrict__ ln2g, const float* __restrict__ ln2b,
                        const float* __restrict__ W2, const float* __restrict__ b2,
                        float* __restrict__ out) {
    int b = blockIdx.x, tid = threadIdx.x;
    __shared__ float pooled[DD];
    __shared__ float t1[HH];
    __shared__ float act[HH];
    __shared__ float smu, srstd;

    float R1 = g_R1[b], R2 = g_R2[b];
    for (int d = tid; d < DD; d += 256)
        pooled[d] = ln1g[d] * ((g_A[b * DD + d] + g_c[b * DD + d] * R1 - R2) * (1.f / TT)) + ln1b[d];
    __syncthreads();

    if (tid < HH) {
        float acc = b1[tid];
        #pragma unroll 8
        for (int d = 0; d < DD; d++) acc += pooled[d] * W1[tid * DD + d];
        t1[tid] = acc;
    }
    __syncthreads();

    if (tid == 0) {
        float mu = 0.f;
        for (int h = 0; h < HH; h++) mu += t1[h];
        mu *= (1.f / HH);
        float var = 0.f;
        for (int h = 0; h < HH; h++) { float dd = t1[h] - mu; var += dd * dd; }
        var *= (1.f / HH);
        smu = mu;
        srstd = rsqrtf(var + 1e-5f);
    }
    __syncthreads();

    if (tid < HH) {
        float v = (t1[tid] - smu) * srstd * ln2g[tid] + ln2b[tid];
        act[tid] = v > 0.f ? v : (expf(v) - 1.f);  // ELU
    }
    __syncthreads();

    if (tid < CC) {
        float acc = b2[tid];
        #pragma unroll
        for (int h = 0; h < HH; h++) acc += act[h] * W2[tid * HH + h];
        out[b * CC + tid] = acc;
    }
}

extern "C" void kernel_launch(void* const* d_in, const int* in_sizes, int n_in,
                              void* d_out, int out_size) {
    const float* tcf  = (const float*)d_in[0];
    const float* gaf  = (const float*)d_in[1];
    const float* Wq   = (const float*)d_in[2];
    const float* Wkv  = (const float*)d_in[3];
    const float* Wout = (const float*)d_in[4];
    const float* ln1g = (const float*)d_in[5];
    const float* ln1b = (const float*)d_in[6];
    const float* W1   = (const float*)d_in[7];
    const float* b1   = (const float*)d_in[8];
    const float* ln2g = (const float*)d_in[9];
    const float* ln2b = (const float*)d_in[10];
    const float* W2   = (const float*)d_in[11];
    const float* b2   = (const float*)d_in[12];
    float* out = (float*)d_out;

    k1_prep<<<BB, 256>>>(gaf, Wq, Wkv, Wout);
    k2_pass1<<<dim3(TT / 256, BB), 256>>>(tcf);
    k3_softmax<<<BB, 256>>>();
    k4_A<<<dim3(DD, BB), 256>>>(tcf);
    k5_head<<<BB, 256>>>(ln1g, ln1b, W1, b1, ln2g, ln2b, W2, b2, out);
}

// round 2
// speedup vs baseline: 1.0392x; 1.0392x over previous
#include <cuda_runtime.h>
#include <math.h>

#define BB 128
#define DD 512
#define TT 1024
#define GG 256
#define KK 32
#define HH 64
#define CC 4
#define CH 8          // d-chunks for pass1/pass2
#define DCH 64        // d rows per chunk (CH*DCH == DD)

// Scratch (allocation-free rule: __device__ globals)
__device__ float g_KV[BB*KK];
__device__ float g_u[BB*DD];
__device__ float g_c[BB*DD];
__device__ float g_Sc[BB];
__device__ float g_Scc[BB];
__device__ float g_rstd[BB*TT];
__device__ float g_R1[BB];
__device__ float g_R2[BB];
__device__ float g_A[BB*DD];
// partial sums from pass1: 4 stats x CH chunks x B x T  (16 MB)
#define PS ((size_t)CH*BB*TT)
__device__ float g_part[4*CH*BB*TT];

__device__ __forceinline__ float warpSum(float v) {
    #pragma unroll
    for (int o = 16; o > 0; o >>= 1) v += __shfl_xor_sync(0xffffffffu, v, o);
    return v;
}
__device__ __forceinline__ float warpMax(float v) {
    #pragma unroll
    for (int o = 16; o > 0; o >>= 1) v = fmaxf(v, __shfl_xor_sync(0xffffffffu, v, o));
    return v;
}

// ---------------------------------------------------------------------------
// Kernel 1: per-batch tiny precompute.
// KV[b,k] = sum_g gaf[b,g]*Wkv[k,g] ; u[b,d] = sum_k Wq[k,d]*KV[b,k]
// c[b,d]  = sum_k KV[b,k]*Wout[d,k] ; Sc=sum_d c ; Scc=sum_d c^2
// ---------------------------------------------------------------------------
__global__ void k1_prep(const float* __restrict__ gaf, const float* __restrict__ Wq,
                        const float* __restrict__ Wkv, const float* __restrict__ Wout) {
    int b = blockIdx.x, tid = threadIdx.x;
    __shared__ float s_gaf[GG];
    __shared__ float s_kv[KK];
    __shared__ float red1[8], red2[8];

    s_gaf[tid] = gaf[b * GG + tid];
    __syncthreads();

    if (tid < KK) {
        float acc = 0.f;
        #pragma unroll 8
        for (int g = 0; g < GG; g++) acc += s_gaf[g] * Wkv[tid * GG + g];
        s_kv[tid] = acc;
        g_KV[b * KK + tid] = acc;
    }
    __syncthreads();

    float lsc = 0.f, lscc = 0.f;
    for (int d = tid; d < DD; d += 256) {
        float uu = 0.f, cc = 0.f;
        #pragma unroll
        for (int k = 0; k < KK; k++) {
            uu += Wq[k * DD + d] * s_kv[k];
            cc += s_kv[k] * Wout[d * KK + k];
        }
        g_u[b * DD + d] = uu;
        g_c[b * DD + d] = cc;
        lsc += cc; lscc += cc * cc;
    }
    lsc = warpSum(lsc); lscc = warpSum(lscc);
    int wid = tid >> 5, lane = tid & 31;
    if (lane == 0) { red1[wid] = lsc; red2[wid] = lscc; }
    __syncthreads();
    if (tid == 0) {
        float a = 0.f, bb = 0.f;
        for (int i = 0; i < 8; i++) { a += red1[i]; bb += red2[i]; }
        g_Sc[b] = a; g_Scc[b] = bb;
    }
}

// ---------------------------------------------------------------------------
// Kernel 2 (pass 1): row-major float4 streaming over tcf [B,D,T].
// Block = (chunk ch, batch b). Thread owns 4 contiguous t values; loops over
// 64 d-rows keeping dot/s1/s2/sxc (x4) in registers. Writes per-chunk partials.
// ---------------------------------------------------------------------------
__global__ void __launch_bounds__(256) k2_pass1(const float* __restrict__ tcf) {
    int ch = blockIdx.x, b = blockIdx.y, tid = threadIdx.x;
    __shared__ float2 s_uc[DCH];

    if (tid < DCH) {
        int d = ch * DCH + tid;
        s_uc[tid] = make_float2(g_u[b * DD + d], g_c[b * DD + d]);
    }
    __syncthreads();

    const float4* xp = (const float4*)(tcf + ((size_t)b * DD + (size_t)ch * DCH) * TT) + tid;
    float4 dot = {0,0,0,0}, s1 = {0,0,0,0}, s2 = {0,0,0,0}, sxc = {0,0,0,0};

    #pragma unroll 4
    for (int r = 0; r < DCH; r++) {
        float4 xv = xp[(size_t)r * (TT/4)];
        float2 uc = s_uc[r];
        dot.x += xv.x*uc.x; dot.y += xv.y*uc.x; dot.z += xv.z*uc.x; dot.w += xv.w*uc.x;
        s1.x  += xv.x;      s1.y  += xv.y;      s1.z  += xv.z;      s1.w  += xv.w;
        s2.x  += xv.x*xv.x; s2.y  += xv.y*xv.y; s2.z  += xv.z*xv.z; s2.w  += xv.w*xv.w;
        sxc.x += xv.x*uc.y; sxc.y += xv.y*uc.y; sxc.z += xv.z*uc.y; sxc.w += xv.w*uc.y;
    }

    size_t base = ((size_t)ch * BB + b) * TT + (size_t)tid * 4;
    *(float4*)(g_part + 0*PS + base) = dot;
    *(float4*)(g_part + 1*PS + base) = s1;
    *(float4*)(g_part + 2*PS + base) = s2;
    *(float4*)(g_part + 3*PS + base) = sxc;
}

// ---------------------------------------------------------------------------
// Kernel 3: reduce partials, softmax over T per b, rstd per (b,t), R1/R2.
// Thread owns 4 contiguous t values (t = 4*tid .. 4*tid+3).
// ---------------------------------------------------------------------------
__global__ void k3_softmax() {
    int b = blockIdx.x, tid = threadIdx.x;
    int wid = tid >> 5, lane = tid & 31;
    __shared__ float red[8], redb[8];
    __shared__ float bval;

    float4 dot = {0,0,0,0}, s1 = {0,0,0,0}, s2 = {0,0,0,0}, sxc = {0,0,0,0};
    #pragma unroll
    for (int ch = 0; ch < CH; ch++) {
        size_t base = ((size_t)ch * BB + b) * TT + (size_t)tid * 4;
        float4 a = *(const float4*)(g_part + 0*PS + base);
        float4 c = *(const float4*)(g_part + 1*PS + base);
        float4 d = *(const float4*)(g_part + 2*PS + base);
        float4 e = *(const float4*)(g_part + 3*PS + base);
        dot.x+=a.x; dot.y+=a.y; dot.z+=a.z; dot.w+=a.w;
        s1.x +=c.x; s1.y +=c.y; s1.z +=c.z; s1.w +=c.w;
        s2.x +=d.x; s2.y +=d.y; s2.z +=d.z; s2.w +=d.w;
        sxc.x+=e.x; sxc.y+=e.y; sxc.z+=e.z; sxc.w+=e.w;
    }

    const float scale = 0.17677669529663687f;  // 1/sqrt(32)
    float sc[4] = {dot.x*scale, dot.y*scale, dot.z*scale, dot.w*scale};
    float vs1[4] = {s1.x, s1.y, s1.z, s1.w};
    float vs2[4] = {s2.x, s2.y, s2.z, s2.w};
    float vsx[4] = {sxc.x, sxc.y, sxc.z, sxc.w};

    float m = fmaxf(fmaxf(sc[0], sc[1]), fmaxf(sc[2], sc[3]));
    m = warpMax(m);
    if (lane == 0) red[wid] = m;
    __syncthreads();
    if (tid == 0) {
        float mm = red[0];
        for (int i = 1; i < 8; i++) mm = fmaxf(mm, red[i]);
        bval = mm;
    }
    __syncthreads();
    m = bval;

    float e[4], se = 0.f;
    #pragma unroll
    for (int i = 0; i < 4; i++) { e[i] = expf(sc[i] - m); se += e[i]; }
    se = warpSum(se);
    __syncthreads();
    if (lane == 0) red[wid] = se;
    __syncthreads();
    if (tid == 0) {
        float s = 0.f;
        for (int i = 0; i < 8; i++) s += red[i];
        bval = s;
    }
    __syncthreads();
    float inv = 1.f / bval;

    float Scb = g_Sc[b], Sccb = g_Scc[b];
    float r1 = 0.f, r2 = 0.f;
    float rst[4];
    #pragma unroll
    for (int i = 0; i < 4; i++) {
        float w = e[i] * inv;
        float mu = (vs1[i] + w * Scb) * (1.f / DD);
        float ms = (vs2[i] + 2.f * w * vsx[i] + w * w * Sccb) * (1.f / DD);
        float var = ms - mu * mu;
        float rstd = rsqrtf(var + 1e-5f);
        rst[i] = rstd;
        r1 += rstd * w;
        r2 += rstd * mu;
    }
    *(float4*)(g_rstd + b * TT + tid * 4) = make_float4(rst[0], rst[1], rst[2], rst[3]);

    r1 = warpSum(r1); r2 = warpSum(r2);
    __syncthreads();
    if (lane == 0) { red[wid] = r1; redb[wid] = r2; }
    __syncthreads();
    if (tid == 0) {
        float a = 0.f, c = 0.f;
        for (int i = 0; i < 8; i++) { a += red[i]; c += redb[i]; }
        g_R1[b] = a; g_R2[b] = c;
    }
}

// ---------------------------------------------------------------------------
// Kernel 4 (pass 2): A[b,d] = sum_t rstd[b,t]*x[b,d,t].
// Block = (chunk ch, batch b) handling 64 d-rows; rstd staged in smem once.
// Warp w owns rows w*8 .. w*8+7 within the chunk; float4 loads along T.
// ---------------------------------------------------------------------------
__global__ void __launch_bounds__(256) k4_A(const float* __restrict__ tcf) {
    int ch = blockIdx.x, b = blockIdx.y, tid = threadIdx.x;
    int w = tid >> 5, lane = tid & 31;
    __shared__ float4 s_r[TT/4];   // 4 KB

    s_r[tid] = ((const float4*)(g_rstd + b * TT))[tid];
    __syncthreads();

    #pragma unroll
    for (int rr = 0; rr < 8; rr++) {
        int d = ch * DCH + w * 8 + rr;
        const float4* xp = (const float4*)(tcf + ((size_t)b * DD + d) * TT);
        float acc = 0.f;
        #pragma unroll
        for (int j = 0; j < 8; j++) {
            float4 xv = xp[lane + j * 32];
            float4 rv = s_r[lane + j * 32];
            acc += xv.x*rv.x + xv.y*rv.y + xv.z*rv.z + xv.w*rv.w;
        }
        acc = warpSum(acc);
        if (lane == 0) g_A[b * DD + d] = acc;
    }
}

// ---------------------------------------------------------------------------
// Kernel 5: pooled + MLP head + output.
// ---------------------------------------------------------------------------
__global__ void k5_head(const float* __restrict__ ln1g, const float* __restrict__ ln1b,
                        const float* __restrict__ W1, const float* __restrict__ b1,
                        const float* __restrict__ ln2g, const float* __restrict__ ln2b,
                        const float* __restrict__ W2, const float* __restrict__ b2,
                        float* __restrict__ out) {
    int b = blockIdx.x, tid = threadIdx.x;
    __shared__ float pooled[DD];
    __shared__ float t1[HH];
    __shared__ float act[HH];
    __shared__ float smu, srstd;

    float R1 = g_R1[b], R2 = g_R2[b];
    for (int d = tid; d < DD; d += 256)
        pooled[d] = ln1g[d] * ((g_A[b * DD + d] + g_c[b * DD + d] * R1 - R2) * (1.f / TT)) + ln1b[d];
    __syncthreads();

    if (tid < HH) {
        float acc = b1[tid];
        #pragma unroll 8
        for (int d = 0; d < DD; d++) acc += pooled[d] * W1[tid * DD + d];
        t1[tid] = acc;
    }
    __syncthreads();

    if (tid == 0) {
        float mu = 0.f;
        for (int h = 0; h < HH; h++) mu += t1[h];
        mu *= (1.f / HH);
        float var = 0.f;
        for (int h = 0; h < HH; h++) { float dd = t1[h] - mu; var += dd * dd; }
        var *= (1.f / HH);
        smu = mu;
        srstd = rsqrtf(var + 1e-5f);
    }
    __syncthreads();

    if (tid < HH) {
        float v = (t1[tid] - smu) * srstd * ln2g[tid] + ln2b[tid];
        act[tid] = v > 0.f ? v : (expf(v) - 1.f);  // ELU
    }
    __syncthreads();

    if (tid < CC) {
        float acc = b2[tid];
        #pragma unroll
        for (int h = 0; h < HH; h++) acc += act[h] * W2[tid * HH + h];
        out[b * CC + tid] = acc;
    }
}

extern "C" void kernel_launch(void* const* d_in, const int* in_sizes, int n_in,
                              void* d_out, int out_size) {
    const float* tcf  = (const float*)d_in[0];
    const float* gaf  = (const float*)d_in[1];
    const float* Wq   = (const float*)d_in[2];
    const float* Wkv  = (const float*)d_in[3];
    const float* Wout = (const float*)d_in[4];
    const float* ln1g = (const float*)d_in[5];
    const float* ln1b = (const float*)d_in[6];
    const float* W1   = (const float*)d_in[7];
    const float* b1   = (const float*)d_in[8];
    const float* ln2g = (const float*)d_in[9];
    const float* ln2b = (const float*)d_in[10];
    const float* W2   = (const float*)d_in[11];
    const float* b2   = (const float*)d_in[12];
    float* out = (float*)d_out;

    k1_prep<<<BB, 256>>>(gaf, Wq, Wkv, Wout);
    k2_pass1<<<dim3(CH, BB), 256>>>(tcf);
    k3_softmax<<<BB, 256>>>();
    k4_A<<<dim3(CH, BB), 256>>>(tcf);
    k5_head<<<BB, 256>>>(ln1g, ln1b, W1, b1, ln2g, ln2b, W2, b2, out);
}

// round 4
// speedup vs baseline: 1.1226x; 1.0803x over previous
#include <cuda_runtime.h>
#include <cuda_fp16.h>
#include <cstdint>
#include <math.h>

#define BB 128
#define DD 512
#define TT 1024
#define GG 256
#define KK 32
#define HH 64
#define CC 4
#define CH 8          // CTAs per cluster == d-chunks per batch
#define DCH 64        // d rows per CTA

// Scratch (allocation-free rule: __device__ globals)
__device__ float g_KV[BB*KK];
__device__ float g_u[BB*DD];
__device__ float g_c[BB*DD];
__device__ float g_Sc[BB];
__device__ float g_Scc[BB];
__device__ float g_R1p[BB*CH];
__device__ float g_R2p[BB*CH];
__device__ float g_A[BB*DD];

// dynamic smem layout (bytes)
#define XOFF     0                    // half x[64][1024]        = 131072
#define INBOXOFF 131072               // float4 inbox[8][128]    = 16384
#define RSTDOFF  147456               // float rstd[1024]        = 4096
#define UCOFF    151552               // float2 uc[64]           = 512
#define MAXOFF   152064               // float maxb[8]           = 32
#define DENOFF   152096               // float denb[8]           = 32
#define REDOFF   152128               // float red[32]           = 128
#define SMEM_MAIN 152320

__device__ __forceinline__ float warpSum(float v) {
    #pragma unroll
    for (int o = 16; o > 0; o >>= 1) v += __shfl_xor_sync(0xffffffffu, v, o);
    return v;
}
__device__ __forceinline__ float warpMax(float v) {
    #pragma unroll
    for (int o = 16; o > 0; o >>= 1) v = fmaxf(v, __shfl_xor_sync(0xffffffffu, v, o));
    return v;
}
__device__ __forceinline__ void stc_f4(unsigned int laddr, int rank, float4 v) {
    unsigned int ra;
    asm volatile("mapa.shared::cluster.u32 %0, %1, %2;" : "=r"(ra) : "r"(laddr), "r"(rank));
    asm volatile("st.shared::cluster.v4.f32 [%0], {%1,%2,%3,%4};"
                 :: "r"(ra), "f"(v.x), "f"(v.y), "f"(v.z), "f"(v.w) : "memory");
}
__device__ __forceinline__ void stc_f1(unsigned int laddr, int rank, float v) {
    unsigned int ra;
    asm volatile("mapa.shared::cluster.u32 %0, %1, %2;" : "=r"(ra) : "r"(laddr), "r"(rank));
    asm volatile("st.shared::cluster.f32 [%0], %1;" :: "r"(ra), "f"(v) : "memory");
}
#define CLUSTER_SYNC() do { \
    asm volatile("barrier.cluster.arrive.aligned;" ::: "memory"); \
    asm volatile("barrier.cluster.wait.aligned;" ::: "memory"); \
} while (0)

// ---------------------------------------------------------------------------
// Kernel 1: per-batch tiny precompute.
// ---------------------------------------------------------------------------
__global__ void k1_prep(const float* __restrict__ gaf, const float* __restrict__ Wq,
                        const float* __restrict__ Wkv, const float* __restrict__ Wout) {
    int b = blockIdx.x, tid = threadIdx.x;
    __shared__ float s_gaf[GG];
    __shared__ float s_kv[KK];
    __shared__ float red1[8], red2[8];

    s_gaf[tid] = gaf[b * GG + tid];
    __syncthreads();

    if (tid < KK) {
        float acc = 0.f;
        #pragma unroll 8
        for (int g = 0; g < GG; g++) acc += s_gaf[g] * Wkv[tid * GG + g];
        s_kv[tid] = acc;
        g_KV[b * KK + tid] = acc;
    }
    __syncthreads();

    float lsc = 0.f, lscc = 0.f;
    for (int d = tid; d < DD; d += 256) {
        float uu = 0.f, cc = 0.f;
        #pragma unroll
        for (int k = 0; k < KK; k++) {
            uu += Wq[k * DD + d] * s_kv[k];
            cc += s_kv[k] * Wout[d * KK + k];
        }
        g_u[b * DD + d] = uu;
        g_c[b * DD + d] = cc;
        lsc += cc; lscc += cc * cc;
    }
    lsc = warpSum(lsc); lscc = warpSum(lscc);
    int wid = tid >> 5, lane = tid & 31;
    if (lane == 0) { red1[wid] = lsc; red2[wid] = lscc; }
    __syncthreads();
    if (tid == 0) {
        float a = 0.f, bb = 0.f;
        for (int i = 0; i < 8; i++) { a += red1[i]; bb += red2[i]; }
        g_Sc[b] = a; g_Scc[b] = bb;
    }
}

// ---------------------------------------------------------------------------
// Fused main kernel: cluster of 8 CTAs per batch. Single DRAM pass over tcf.
// Phase 1: stream 64 d-rows, stash fp16 x in smem, per-t stat partials.
// DSMEM exchange: stats -> softmax scalars -> rstd. Phase 2: A from smem.
// ---------------------------------------------------------------------------
__global__ void __launch_bounds__(256, 1) __cluster_dims__(CH, 1, 1)
k_main(const float* __restrict__ tcf) {
    extern __shared__ char smem[];
    half*   x_h    = (half*)(smem + XOFF);
    float4* inbox  = (float4*)(smem + INBOXOFF);
    float*  rstd_s = (float*)(smem + RSTDOFF);
    float2* uc     = (float2*)(smem + UCOFF);
    float*  maxb   = (float*)(smem + MAXOFF);
    float*  denb   = (float*)(smem + DENOFF);
    float*  red    = (float*)(smem + REDOFF);

    const int rank = blockIdx.x;      // d-chunk index within batch
    const int b    = blockIdx.y;
    const int tid  = threadIdx.x;
    const int lane = tid & 31, w = tid >> 5;

    unsigned int smem_u32 = (unsigned int)__cvta_generic_to_shared(smem);

    if (tid < DCH) {
        int d = rank * DCH + tid;
        uc[tid] = make_float2(g_u[b * DD + d], g_c[b * DD + d]);
    }
    __syncthreads();

    // ---- Phase 1: stream own chunk (64 rows x 1024 t), fp32 stats + fp16 stash
    const float4* xp = (const float4*)(tcf + ((size_t)b * DD + (size_t)rank * DCH) * TT) + tid;
    float4 dot = {0,0,0,0}, s1 = {0,0,0,0}, s2 = {0,0,0,0}, sxc = {0,0,0,0};

    #pragma unroll 16
    for (int r = 0; r < DCH; r++) {
        float4 xv = xp[r * (TT/4)];
        float2 u_ = uc[r];
        dot.x += xv.x*u_.x; dot.y += xv.y*u_.x; dot.z += xv.z*u_.x; dot.w += xv.w*u_.x;
        s1.x  += xv.x;      s1.y  += xv.y;      s1.z  += xv.z;      s1.w  += xv.w;
        s2.x  += xv.x*xv.x; s2.y  += xv.y*xv.y; s2.z  += xv.z*xv.z; s2.w  += xv.w*xv.w;
        sxc.x += xv.x*u_.y; sxc.y += xv.y*u_.y; sxc.z += xv.z*u_.y; sxc.w += xv.w*u_.y;
        half2 h01 = __floats2half2_rn(xv.x, xv.y);
        half2 h23 = __floats2half2_rn(xv.z, xv.w);
        uint2 pk;
        pk.x = *reinterpret_cast<unsigned int*>(&h01);
        pk.y = *reinterpret_cast<unsigned int*>(&h23);
        ((uint2*)(x_h + r * TT))[tid] = pk;
    }

    // ---- Send per-t stat partials to owner CTA (dest rank = warp id).
    // Thread owns t in [4*tid, 4*tid+4); t_local within dest = 4*lane..4*lane+3.
    {
        unsigned int addr = smem_u32 + INBOXOFF + (unsigned int)(rank * 128 + lane * 4) * 16;
        int dst = w;
        stc_f4(addr,      dst, make_float4(dot.x, s1.x, s2.x, sxc.x));
        stc_f4(addr + 16, dst, make_float4(dot.y, s1.y, s2.y, sxc.y));
        stc_f4(addr + 32, dst, make_float4(dot.z, s1.z, s2.z, sxc.z));
        stc_f4(addr + 48, dst, make_float4(dot.w, s1.w, s2.w, sxc.w));
    }
    CLUSTER_SYNC();

    // ---- Reduce stats for own 128 t's (threads 0..127: t_local = tid)
    float score = 0.f, v1 = 0.f, v2 = 0.f, vx = 0.f;
    if (tid < 128) {
        float4 acc = {0,0,0,0};
        #pragma unroll
        for (int s = 0; s < CH; s++) {
            float4 v = inbox[s * 128 + tid];
            acc.x += v.x; acc.y += v.y; acc.z += v.z; acc.w += v.w;
        }
        score = acc.x * 0.17677669529663687f;   // 1/sqrt(32)
        v1 = acc.y; v2 = acc.z; vx = acc.w;
        float m = warpMax(score);
        if (lane == 0) red[w] = m;
    }
    __syncthreads();
    if (tid == 0) {
        float m = fmaxf(fmaxf(red[0], red[1]), fmaxf(red[2], red[3]));
        unsigned int la = smem_u32 + MAXOFF + rank * 4;
        #pragma unroll
        for (int dst = 0; dst < CH; dst++) stc_f1(la, dst, m);
    }
    CLUSTER_SYNC();

    float M = fmaxf(fmaxf(fmaxf(maxb[0], maxb[1]), fmaxf(maxb[2], maxb[3])),
                    fmaxf(fmaxf(maxb[4], maxb[5]), fmaxf(maxb[6], maxb[7])));
    float e = 0.f;
    if (tid < 128) {
        e = expf(score - M);
        float se = warpSum(e);
        if (lane == 0) red[w] = se;
    }
    __syncthreads();
    if (tid == 0) {
        float s = red[0] + red[1] + red[2] + red[3];
        unsigned int la = smem_u32 + DENOFF + rank * 4;
        #pragma unroll
        for (int dst = 0; dst < CH; dst++) stc_f1(la, dst, s);
    }
    CLUSTER_SYNC();

    float denom = denb[0]+denb[1]+denb[2]+denb[3]+denb[4]+denb[5]+denb[6]+denb[7];
    if (tid < 128) {
        float wgt = e / denom;
        float Scb = g_Sc[b], Sccb = g_Scc[b];
        float mu = (v1 + wgt * Scb) * (1.f / DD);
        float ms = (v2 + 2.f * wgt * vx + wgt * wgt * Sccb) * (1.f / DD);
        float rs = rsqrtf(ms - mu * mu + 1e-5f);
        int tg = rank * 128 + tid;
        unsigned int la = smem_u32 + RSTDOFF + (unsigned int)tg * 4;
        #pragma unroll
        for (int dst = 0; dst < CH; dst++) stc_f1(la, dst, rs);
        float r1 = warpSum(rs * wgt);
        float r2 = warpSum(rs * mu);
        if (lane == 0) { red[w] = r1; red[8 + w] = r2; }
    }
    __syncthreads();
    if (tid == 0) {
        g_R1p[b * CH + rank] = red[0] + red[1] + red[2] + red[3];
        g_R2p[b * CH + rank] = red[8] + red[9] + red[10] + red[11];
    }
    CLUSTER_SYNC();   // all rstd values delivered everywhere

    // ---- Phase 2: A[d] = sum_t rstd[t] * x[d,t] from smem fp16 stash.
    // Warp w owns rows w*8..w*8+7.
    #pragma unroll
    for (int rr = 0; rr < 8; rr++) {
        int row = w * 8 + rr;
        const uint2* xr = (const uint2*)(x_h + row * TT);
        float acc = 0.f;
        #pragma unroll
        for (int j = 0; j < 8; j++) {
            int t0 = j * 128 + lane * 4;
            uint2 pk = xr[t0 >> 2];
            half2 h01 = *reinterpret_cast<half2*>(&pk.x);
            half2 h23 = *reinterpret_cast<half2*>(&pk.y);
            float2 f01 = __half22float2(h01);
            float2 f23 = __half22float2(h23);
            float4 rv = *(const float4*)(rstd_s + t0);
            acc += f01.x * rv.x + f01.y * rv.y + f23.x * rv.z + f23.y * rv.w;
        }
        acc = warpSum(acc);
        if (lane == 0) g_A[b * DD + rank * DCH + row] = acc;
    }
}

// ---------------------------------------------------------------------------
// Kernel 5: pooled + MLP head + output (R1/R2 from partials).
// ---------------------------------------------------------------------------
__global__ void k5_head(const float* __restrict__ ln1g, const float* __restrict__ ln1b,
                        const float* __restrict__ W1, const float* __restrict__ b1,
                        const float* __restrict__ ln2g, const float* __restrict__ ln2b,
                        const float* __restrict__ W2, const float* __restrict__ b2,
                        float* __restrict__ out) {
    int b = blockIdx.x, tid = threadIdx.x;
    __shared__ float pooled[DD];
    __shared__ float t1[HH];
    __shared__ float act[HH];
    __shared__ float smu, srstd;

    float R1 = 0.f, R2 = 0.f;
    #pragma unroll
    for (int i = 0; i < CH; i++) { R1 += g_R1p[b * CH + i]; R2 += g_R2p[b * CH + i]; }

    for (int d = tid; d < DD; d += 256)
        pooled[d] = ln1g[d] * ((g_A[b * DD + d] + g_c[b * DD + d] * R1 - R2) * (1.f / TT)) + ln1b[d];
    __syncthreads();

    if (tid < HH) {
        float acc = b1[tid];
        #pragma unroll 8
        for (int d = 0; d < DD; d++) acc += pooled[d] * W1[tid * DD + d];
        t1[tid] = acc;
    }
    __syncthreads();

    if (tid == 0) {
        float mu = 0.f;
        for (int h = 0; h < HH; h++) mu += t1[h];
        mu *= (1.f / HH);
        float var = 0.f;
        for (int h = 0; h < HH; h++) { float dd = t1[h] - mu; var += dd * dd; }
        var *= (1.f / HH);
        smu = mu;
        srstd = rsqrtf(var + 1e-5f);
    }
    __syncthreads();

    if (tid < HH) {
        float v = (t1[tid] - smu) * srstd * ln2g[tid] + ln2b[tid];
        act[tid] = v > 0.f ? v : (expf(v) - 1.f);  // ELU
    }
    __syncthreads();

    if (tid < CC) {
        float acc = b2[tid];
        #pragma unroll
        for (int h = 0; h < HH; h++) acc += act[h] * W2[tid * HH + h];
        out[b * CC + tid] = acc;
    }
}

extern "C" void kernel_launch(void* const* d_in, const int* in_sizes, int n_in,
                              void* d_out, int out_size) {
    const float* tcf  = (const float*)d_in[0];
    const float* gaf  = (const float*)d_in[1];
    const float* Wq   = (const float*)d_in[2];
    const float* Wkv  = (const float*)d_in[3];
    const float* Wout = (const float*)d_in[4];
    const float* ln1g = (const float*)d_in[5];
    const float* ln1b = (const float*)d_in[6];
    const float* W1   = (const float*)d_in[7];
    const float* b1   = (const float*)d_in[8];
    const float* ln2g = (const float*)d_in[9];
    const float* ln2b = (const float*)d_in[10];
    const float* W2   = (const float*)d_in[11];
    const float* b2   = (const float*)d_in[12];
    float* out = (float*)d_out;

    cudaFuncSetAttribute(k_main, cudaFuncAttributeMaxDynamicSharedMemorySize, SMEM_MAIN);

    k1_prep<<<BB, 256>>>(gaf, Wq, Wkv, Wout);
    k_main<<<dim3(CH, BB), 256, SMEM_MAIN>>>(tcf);
    k5_head<<<BB, 256>>>(ln1g, ln1b, W1, b1, ln2g, ln2b, W2, b2, out);
}

// round 5
// speedup vs baseline: 1.4165x; 1.2618x over previous
#include <cuda_runtime.h>
#include <cuda_fp16.h>
#include <cstdint>
#include <math.h>

#define BB 128
#define DD 512
#define TT 1024
#define GG 256
#define KK 32
#define HH 64
#define CC 4
#define CH 8          // CTAs per cluster == d-chunks per batch
#define DCH 64        // d rows per CTA

// Scratch (allocation-free rule: __device__ globals)
__device__ float g_u[BB*DD];
__device__ float g_c[BB*DD];
__device__ float g_Sc[BB];
__device__ float g_Scc[BB];
__device__ float g_R1p[BB*CH];
__device__ float g_R2p[BB*CH];
__device__ float g_A[BB*DD];

// dynamic smem layout (bytes)
#define XOFF     0                    // half x[64][1024]        = 131072
#define INBOXOFF 131072               // float4 inbox[8][128]    = 16384
#define RSTDOFF  147456               // float rstd[1024]        = 4096
#define UCOFF    151552               // float2 uc[64]           = 512
#define MAXOFF   152064               // float maxb[8]           = 32
#define DENOFF   152096               // float denb[8]           = 32
#define REDOFF   152128               // float red[32]           = 128
#define SMEM_MAIN 152320

__device__ __forceinline__ float warpSum(float v) {
    #pragma unroll
    for (int o = 16; o > 0; o >>= 1) v += __shfl_xor_sync(0xffffffffu, v, o);
    return v;
}
__device__ __forceinline__ float warpMax(float v) {
    #pragma unroll
    for (int o = 16; o > 0; o >>= 1) v = fmaxf(v, __shfl_xor_sync(0xffffffffu, v, o));
    return v;
}
__device__ __forceinline__ void stc_f4(unsigned int laddr, int rank, float4 v) {
    unsigned int ra;
    asm volatile("mapa.shared::cluster.u32 %0, %1, %2;" : "=r"(ra) : "r"(laddr), "r"(rank));
    asm volatile("st.shared::cluster.v4.f32 [%0], {%1,%2,%3,%4};"
                 :: "r"(ra), "f"(v.x), "f"(v.y), "f"(v.z), "f"(v.w) : "memory");
}
__device__ __forceinline__ void stc_f1(unsigned int laddr, int rank, float v) {
    unsigned int ra;
    asm volatile("mapa.shared::cluster.u32 %0, %1, %2;" : "=r"(ra) : "r"(laddr), "r"(rank));
    asm volatile("st.shared::cluster.f32 [%0], %1;" :: "r"(ra), "f"(v) : "memory");
}
#define CLUSTER_SYNC() do { \
    asm volatile("barrier.cluster.arrive.aligned;" ::: "memory"); \
    asm volatile("barrier.cluster.wait.aligned;" ::: "memory"); \
} while (0)

// ---------------------------------------------------------------------------
// Kernel 1: per-batch precompute — all loads warp-coalesced now.
// KV[k] = sum_g gaf[g]*Wkv[k,g] ; u[d] = sum_k Wq[k,d]*KV[k]
// c[d]  = sum_k KV[k]*Wout[d,k] ; Sc = sum_d c ; Scc = sum_d c^2
// ---------------------------------------------------------------------------
__global__ void k1_prep(const float* __restrict__ gaf, const float* __restrict__ Wq,
                        const float* __restrict__ Wkv, const float* __restrict__ Wout) {
    int b = blockIdx.x, tid = threadIdx.x;
    int w = tid >> 5, lane = tid & 31;
    __shared__ float s_gaf[GG];
    __shared__ float s_kv[KK];
    __shared__ float red1[8], red2[8];

    s_gaf[tid] = gaf[b * GG + tid];
    __syncthreads();

    // warp w computes k = 4w .. 4w+3, lanes sweep g coalesced
    #pragma unroll
    for (int kk = 0; kk < 4; kk++) {
        int k = w * 4 + kk;
        float acc = 0.f;
        #pragma unroll
        for (int i = 0; i < 8; i++) {
            int g = lane + 32 * i;
            acc += s_gaf[g] * Wkv[k * GG + g];
        }
        acc = warpSum(acc);
        if (lane == 0) s_kv[k] = acc;
    }
    __syncthreads();

    float lsc = 0.f, lscc = 0.f;
    #pragma unroll
    for (int it = 0; it < 2; it++) {
        int d = tid + it * 256;
        float uu = 0.f, cc = 0.f;
        #pragma unroll
        for (int k = 0; k < KK; k++) {
            uu += Wq[k * DD + d] * s_kv[k];       // coalesced across threads
            cc += s_kv[k] * Wout[d * KK + k];     // L1-resident after first pass
        }
        g_u[b * DD + d] = uu;
        g_c[b * DD + d] = cc;
        lsc += cc; lscc += cc * cc;
    }
    lsc = warpSum(lsc); lscc = warpSum(lscc);
    if (lane == 0) { red1[w] = lsc; red2[w] = lscc; }
    __syncthreads();
    if (tid == 0) {
        float a = 0.f, bb = 0.f;
        for (int i = 0; i < 8; i++) { a += red1[i]; bb += red2[i]; }
        g_Sc[b] = a; g_Scc[b] = bb;
    }
}

// ---------------------------------------------------------------------------
// Fused main kernel: cluster of 8 CTAs per batch. Single DRAM pass over tcf.
// ---------------------------------------------------------------------------
__global__ void __launch_bounds__(256, 1) __cluster_dims__(CH, 1, 1)
k_main(const float* __restrict__ tcf) {
    extern __shared__ char smem[];
    half*   x_h    = (half*)(smem + XOFF);
    float4* inbox  = (float4*)(smem + INBOXOFF);
    float*  rstd_s = (float*)(smem + RSTDOFF);
    float2* uc     = (float2*)(smem + UCOFF);
    float*  maxb   = (float*)(smem + MAXOFF);
    float*  denb   = (float*)(smem + DENOFF);
    float*  red    = (float*)(smem + REDOFF);

    const int rank = blockIdx.x;      // d-chunk index within batch
    const int b    = blockIdx.y;
    const int tid  = threadIdx.x;
    const int lane = tid & 31, w = tid >> 5;

    unsigned int smem_u32 = (unsigned int)__cvta_generic_to_shared(smem);

    if (tid < DCH) {
        int d = rank * DCH + tid;
        uc[tid] = make_float2(g_u[b * DD + d], g_c[b * DD + d]);
    }
    __syncthreads();

    // ---- Phase 1: stream own chunk (64 rows x 1024 t), fp32 stats + fp16 stash
    const float4* xp = (const float4*)(tcf + ((size_t)b * DD + (size_t)rank * DCH) * TT) + tid;
    float4 dot = {0,0,0,0}, s1 = {0,0,0,0}, s2 = {0,0,0,0}, sxc = {0,0,0,0};

    #pragma unroll 16
    for (int r = 0; r < DCH; r++) {
        float4 xv = xp[r * (TT/4)];
        float2 u_ = uc[r];
        dot.x += xv.x*u_.x; dot.y += xv.y*u_.x; dot.z += xv.z*u_.x; dot.w += xv.w*u_.x;
        s1.x  += xv.x;      s1.y  += xv.y;      s1.z  += xv.z;      s1.w  += xv.w;
        s2.x  += xv.x*xv.x; s2.y  += xv.y*xv.y; s2.z  += xv.z*xv.z; s2.w  += xv.w*xv.w;
        sxc.x += xv.x*u_.y; sxc.y += xv.y*u_.y; sxc.z += xv.z*u_.y; sxc.w += xv.w*u_.y;
        half2 h01 = __floats2half2_rn(xv.x, xv.y);
        half2 h23 = __floats2half2_rn(xv.z, xv.w);
        uint2 pk;
        pk.x = *reinterpret_cast<unsigned int*>(&h01);
        pk.y = *reinterpret_cast<unsigned int*>(&h23);
        ((uint2*)(x_h + r * TT))[tid] = pk;
    }

    // ---- Send per-t stat partials to owner CTA (dest rank = warp id).
    {
        unsigned int addr = smem_u32 + INBOXOFF + (unsigned int)(rank * 128 + lane * 4) * 16;
        int dst = w;
        stc_f4(addr,      dst, make_float4(dot.x, s1.x, s2.x, sxc.x));
        stc_f4(addr + 16, dst, make_float4(dot.y, s1.y, s2.y, sxc.y));
        stc_f4(addr + 32, dst, make_float4(dot.z, s1.z, s2.z, sxc.z));
        stc_f4(addr + 48, dst, make_float4(dot.w, s1.w, s2.w, sxc.w));
    }
    CLUSTER_SYNC();

    // ---- Reduce stats for own 128 t's (threads 0..127: t_local = tid)
    float score = 0.f, v1 = 0.f, v2 = 0.f, vx = 0.f;
    if (tid < 128) {
        float4 acc = {0,0,0,0};
        #pragma unroll
        for (int s = 0; s < CH; s++) {
            float4 v = inbox[s * 128 + tid];
            acc.x += v.x; acc.y += v.y; acc.z += v.z; acc.w += v.w;
        }
        score = acc.x * 0.17677669529663687f;   // 1/sqrt(32)
        v1 = acc.y; v2 = acc.z; vx = acc.w;
        float m = warpMax(score);
        if (lane == 0) red[w] = m;
    }
    __syncthreads();
    if (tid == 0) {
        float m = fmaxf(fmaxf(red[0], red[1]), fmaxf(red[2], red[3]));
        unsigned int la = smem_u32 + MAXOFF + rank * 4;
        #pragma unroll
        for (int dst = 0; dst < CH; dst++) stc_f1(la, dst, m);
    }
    CLUSTER_SYNC();

    float M = fmaxf(fmaxf(fmaxf(maxb[0], maxb[1]), fmaxf(maxb[2], maxb[3])),
                    fmaxf(fmaxf(maxb[4], maxb[5]), fmaxf(maxb[6], maxb[7])));
    float e = 0.f;
    if (tid < 128) {
        e = expf(score - M);
        float se = warpSum(e);
        if (lane == 0) red[w] = se;
    }
    __syncthreads();
    if (tid == 0) {
        float s = red[0] + red[1] + red[2] + red[3];
        unsigned int la = smem_u32 + DENOFF + rank * 4;
        #pragma unroll
        for (int dst = 0; dst < CH; dst++) stc_f1(la, dst, s);
    }
    CLUSTER_SYNC();

    float denom = denb[0]+denb[1]+denb[2]+denb[3]+denb[4]+denb[5]+denb[6]+denb[7];
    if (tid < 128) {
        float wgt = e / denom;
        float Scb = g_Sc[b], Sccb = g_Scc[b];
        float mu = (v1 + wgt * Scb) * (1.f / DD);
        float ms = (v2 + 2.f * wgt * vx + wgt * wgt * Sccb) * (1.f / DD);
        float rs = rsqrtf(ms - mu * mu + 1e-5f);
        int tg = rank * 128 + tid;
        unsigned int la = smem_u32 + RSTDOFF + (unsigned int)tg * 4;
        #pragma unroll
        for (int dst = 0; dst < CH; dst++) stc_f1(la, dst, rs);
        float r1 = warpSum(rs * wgt);
        float r2 = warpSum(rs * mu);
        if (lane == 0) { red[w] = r1; red[8 + w] = r2; }
    }
    __syncthreads();
    if (tid == 0) {
        g_R1p[b * CH + rank] = red[0] + red[1] + red[2] + red[3];
        g_R2p[b * CH + rank] = red[8] + red[9] + red[10] + red[11];
    }
    CLUSTER_SYNC();   // all rstd values delivered everywhere

    // ---- Phase 2: A[d] = sum_t rstd[t] * x[d,t] from smem fp16 stash.
    #pragma unroll
    for (int rr = 0; rr < 8; rr++) {
        int row = w * 8 + rr;
        const uint2* xr = (const uint2*)(x_h + row * TT);
        float acc = 0.f;
        #pragma unroll
        for (int j = 0; j < 8; j++) {
            int t0 = j * 128 + lane * 4;
            uint2 pk = xr[t0 >> 2];
            half2 h01 = *reinterpret_cast<half2*>(&pk.x);
            half2 h23 = *reinterpret_cast<half2*>(&pk.y);
            float2 f01 = __half22float2(h01);
            float2 f23 = __half22float2(h23);
            float4 rv = *(const float4*)(rstd_s + t0);
            acc += f01.x * rv.x + f01.y * rv.y + f23.x * rv.z + f23.y * rv.w;
        }
        acc = warpSum(acc);
        if (lane == 0) g_A[b * DD + rank * DCH + row] = acc;
    }
}

// ---------------------------------------------------------------------------
// Kernel 5: pooled + MLP head + output — fully warp-parallel now.
// ---------------------------------------------------------------------------
__global__ void k5_head(const float* __restrict__ ln1g, const float* __restrict__ ln1b,
                        const float* __restrict__ W1, const float* __restrict__ b1,
                        const float* __restrict__ ln2g, const float* __restrict__ ln2b,
                        const float* __restrict__ W2, const float* __restrict__ b2,
                        float* __restrict__ out) {
    int b = blockIdx.x, tid = threadIdx.x;
    int w = tid >> 5, lane = tid & 31;
    __shared__ float pooled[DD];
    __shared__ float t1[HH];
    __shared__ float act[HH];
    __shared__ float smu, srstd;

    float R1 = 0.f, R2 = 0.f;
    #pragma unroll
    for (int i = 0; i < CH; i++) { R1 += g_R1p[b * CH + i]; R2 += g_R2p[b * CH + i]; }

    #pragma unroll
    for (int it = 0; it < 2; it++) {
        int d = tid + it * 256;
        pooled[d] = ln1g[d] * ((g_A[b * DD + d] + g_c[b * DD + d] * R1 - R2) * (1.f / TT)) + ln1b[d];
    }
    __syncthreads();

    // warp w computes h = 8w .. 8w+7, lanes sweep d coalesced
    #pragma unroll
    for (int hh = 0; hh < 8; hh++) {
        int h = w * 8 + hh;
        float acc = 0.f;
        #pragma unroll
        for (int i = 0; i < 16; i++) {
            int d = lane + 32 * i;
            acc += pooled[d] * W1[h * DD + d];
        }
        acc = warpSum(acc);
        if (lane == 0) t1[h] = acc + b1[h];
    }
    __syncthreads();

    // LN2 stats via one warp
    if (w == 0) {
        float a = t1[lane], bb = t1[lane + 32];
        float sum = warpSum(a + bb) * (1.f / HH);
        float sq  = warpSum(a * a + bb * bb) * (1.f / HH);
        if (lane == 0) { smu = sum; srstd = rsqrtf(sq - sum * sum + 1e-5f); }
    }
    __syncthreads();

    if (tid < HH) {
        float v = (t1[tid] - smu) * srstd * ln2g[tid] + ln2b[tid];
        act[tid] = v > 0.f ? v : (expf(v) - 1.f);  // ELU
    }
    __syncthreads();

    // warp w<4 computes class w
    if (w < CC) {
        float acc = act[lane] * W2[w * HH + lane] + act[lane + 32] * W2[w * HH + lane + 32];
        acc = warpSum(acc);
        if (lane == 0) out[b * CC + w] = acc + b2[w];
    }
}

extern "C" void kernel_launch(void* const* d_in, const int* in_sizes, int n_in,
                              void* d_out, int out_size) {
    const float* tcf  = (const float*)d_in[0];
    const float* gaf  = (const float*)d_in[1];
    const float* Wq   = (const float*)d_in[2];
    const float* Wkv  = (const float*)d_in[3];
    const float* Wout = (const float*)d_in[4];
    const float* ln1g = (const float*)d_in[5];
    const float* ln1b = (const float*)d_in[6];
    const float* W1   = (const float*)d_in[7];
    const float* b1   = (const float*)d_in[8];
    const float* ln2g = (const float*)d_in[9];
    const float* ln2b = (const float*)d_in[10];
    const float* W2   = (const float*)d_in[11];
    const float* b2   = (const float*)d_in[12];
    float* out = (float*)d_out;

    cudaFuncSetAttribute(k_main, cudaFuncAttributeMaxDynamicSharedMemorySize, SMEM_MAIN);

    k1_prep<<<BB, 256>>>(gaf, Wq, Wkv, Wout);
    k_main<<<dim3(CH, BB), 256, SMEM_MAIN>>>(tcf);
    k5_head<<<BB, 256>>>(ln1g, ln1b, W1, b1, ln2g, ln2b, W2, b2, out);
}